// round 4
// baseline (speedup 1.0000x reference)
#include <cuda_runtime.h>
#include <cstdint>

// Problem constants
#define Bb   8
#define Nn   1024
#define Cc   512
#define Kk   20
#define Mm   64
#define Pp   (Bb * Nn)        // 8192 points
#define CNT1 (Pp * Kk)        // 163840 samples for BN1
#define CNT2 Pp               // 8192 samples for BN2
#define EPS  1e-5f

// Scratch (no cudaMalloc allowed)
__device__ float g_W1p[128 * 512];      // folded W1' fp32
__device__ float g_y[Pp * 128];         // per-point y1(0:64) | y2(64:128)
__device__ float g_hmax[Pp * 64];
__device__ float g_hmin[Pp * 64];
__device__ float g_part1[256 * 128];    // per-block [sum(64) | sumsq(64)]
__device__ float g_bn1[128];            // scale(64) | bias(64)
__device__ float g_p2s[128 * 512];
__device__ float g_p2q[128 * 512];
__device__ float g_bn2[1024];           // scale(512) | bias(512)

__device__ __forceinline__ float tf32_rna(float v) {
    uint32_t u;
    asm("cvt.rna.tf32.f32 %0, %1;" : "=r"(u) : "f"(v));
    return __uint_as_float(u);
}

__device__ __forceinline__ void mma_tf32(float* d, const float* a, const float* b) {
    asm volatile(
        "mma.sync.aligned.m16n8k8.row.col.f32.tf32.tf32.f32 "
        "{%0,%1,%2,%3}, {%4,%5,%6,%7}, {%8,%9}, {%0,%1,%2,%3};"
        : "+f"(d[0]), "+f"(d[1]), "+f"(d[2]), "+f"(d[3])
        : "r"(__float_as_uint(a[0])), "r"(__float_as_uint(a[1])),
          "r"(__float_as_uint(a[2])), "r"(__float_as_uint(a[3])),
          "r"(__float_as_uint(b[0])), "r"(__float_as_uint(b[1])));
}

// split f32 -> (hi, lo) tf32 pair
__device__ __forceinline__ void tf32_split(float v, float& hi, float& lo) {
    hi = tf32_rna(v);
    lo = tf32_rna(v - hi);
}

// ---------------------------------------------------------------------------
// K0: fold W1 [64][1024] -> W1' [128][512] (fp32)
// ---------------------------------------------------------------------------
__global__ void k0_prepw(const float* __restrict__ W1) {
    int i = blockIdx.x * 256 + threadIdx.x;      // 0 .. 65535
    int n = i >> 9, c = i & 511;
    float v;
    if (n < 64) {
        v = W1[n * 1024 + c];
    } else {
        int m = n - 64;
        v = W1[m * 1024 + 512 + c] - W1[m * 1024 + c];
    }
    g_W1p[i] = v;
}

// ---------------------------------------------------------------------------
// K1: y[8192][128] = x[8192][512] @ W1'^T via tf32 MMA, hi/lo split in regs
// Block: 64 pts x 128 N, BK=16, 256 threads (8 warps, each 32x32)
// ---------------------------------------------------------------------------
__global__ void __launch_bounds__(256) k1_gemm1(const float* __restrict__ x) {
    __shared__ float sx[64][20];
    __shared__ float sw[128][20];

    int tid = threadIdx.x;
    int lane = tid & 31, w = tid >> 5;
    int grp = lane >> 2, tig = lane & 3;
    int m_base = (w >> 2) * 32;     // 0 or 32
    int n_base = (w & 3) * 32;      // 0,32,64,96
    int p0 = blockIdx.x * 64;

    float acc[2][4][4];
#pragma unroll
    for (int r = 0; r < 2; r++)
#pragma unroll
        for (int j = 0; j < 4; j++)
#pragma unroll
            for (int q = 0; q < 4; q++) acc[r][j][q] = 0.f;

    int xrow = tid >> 2;            // 0..63
    int cseg = (tid & 3) * 4;       // 0,4,8,12

    for (int t = 0; t < 32; t++) {
        int k0 = t * 16;
        *reinterpret_cast<float4*>(&sx[xrow][cseg]) =
            *reinterpret_cast<const float4*>(&x[(p0 + xrow) * 512 + k0 + cseg]);
#pragma unroll
        for (int rr = 0; rr < 2; rr++) {
            int wrow = (tid >> 2) + rr * 64;
            *reinterpret_cast<float4*>(&sw[wrow][cseg]) =
                *reinterpret_cast<const float4*>(&g_W1p[wrow * 512 + k0 + cseg]);
        }
        __syncthreads();

#pragma unroll
        for (int ks = 0; ks < 16; ks += 8) {
            float ah[2][4], al[2][4], bh[4][2], bl[4][2];
#pragma unroll
            for (int r = 0; r < 2; r++) {
                int mr = m_base + r * 16;
                float v0 = sx[mr + grp][ks + tig];
                float v1 = sx[mr + grp + 8][ks + tig];
                float v2 = sx[mr + grp][ks + tig + 4];
                float v3 = sx[mr + grp + 8][ks + tig + 4];
                tf32_split(v0, ah[r][0], al[r][0]);
                tf32_split(v1, ah[r][1], al[r][1]);
                tf32_split(v2, ah[r][2], al[r][2]);
                tf32_split(v3, ah[r][3], al[r][3]);
            }
#pragma unroll
            for (int j = 0; j < 4; j++) {
                int nc = n_base + j * 8 + grp;
                float v0 = sw[nc][ks + tig];
                float v1 = sw[nc][ks + tig + 4];
                tf32_split(v0, bh[j][0], bl[j][0]);
                tf32_split(v1, bh[j][1], bl[j][1]);
            }
#pragma unroll
            for (int r = 0; r < 2; r++)
#pragma unroll
                for (int j = 0; j < 4; j++) {
                    mma_tf32(acc[r][j], ah[r], bh[j]);
                    mma_tf32(acc[r][j], al[r], bh[j]);
                    mma_tf32(acc[r][j], ah[r], bl[j]);
                }
        }
        __syncthreads();
    }

#pragma unroll
    for (int r = 0; r < 2; r++) {
        int prow = p0 + m_base + r * 16 + grp;
#pragma unroll
        for (int j = 0; j < 4; j++) {
            int col = n_base + j * 8 + 2 * tig;
            *reinterpret_cast<float2*>(&g_y[prow * 128 + col]) =
                make_float2(acc[r][j][0], acc[r][j][1]);
            *reinterpret_cast<float2*>(&g_y[(prow + 8) * 128 + col]) =
                make_float2(acc[r][j][2], acc[r][j][3]);
        }
    }
}

// ---------------------------------------------------------------------------
// K2: gather over K=20 neighbors: per (p,m) max/min; block-partial sum/sumsq
// ---------------------------------------------------------------------------
__global__ void __launch_bounds__(256) k2_gather(const int* __restrict__ idx) {
    __shared__ int   sidx[4][20];
    __shared__ float red[2][256];
    int tid = threadIdx.x;
    int m = tid & 63, slot = tid >> 6;
    float fs = 0.f, fq = 0.f;
    int pbase = blockIdx.x * 32;

    for (int i = 0; i < 8; i++) {
        int p = pbase + i * 4 + slot;
        if (m < 20) sidx[slot][m] = idx[p * 20 + m];
        __syncthreads();
        float y2 = g_y[p * 128 + 64 + m];
        int rowb = (p & ~1023) * 128;     // batch base row * 128
        float vmax = -1e30f, vmin = 1e30f;
#pragma unroll
        for (int k = 0; k < 20; k++) {
            int g = sidx[slot][k];
            float v = g_y[rowb + g * 128 + m] + y2;
            fs += v;
            fq += v * v;
            vmax = fmaxf(vmax, v);
            vmin = fminf(vmin, v);
        }
        g_hmax[p * 64 + m] = vmax;
        g_hmin[p * 64 + m] = vmin;
        __syncthreads();
    }
    red[0][tid] = fs;
    red[1][tid] = fq;
    __syncthreads();
    if (tid < 64) {
        float s = red[0][tid] + red[0][tid + 64] + red[0][tid + 128] + red[0][tid + 192];
        float q = red[1][tid] + red[1][tid + 64] + red[1][tid + 128] + red[1][tid + 192];
        g_part1[blockIdx.x * 128 + tid] = s;
        g_part1[blockIdx.x * 128 + 64 + tid] = q;
    }
}

// ---------------------------------------------------------------------------
// K3: finalize BN1 — 64 blocks, one channel pair per block, 256 threads
// ---------------------------------------------------------------------------
__global__ void __launch_bounds__(256) k3_stats1(const float* __restrict__ gamma1,
                                                 const float* __restrict__ beta1) {
    __shared__ float ss[256];
    __shared__ float sq[256];
    int tid = threadIdx.x;
    int m = blockIdx.x;                       // 0..63
    ss[tid] = g_part1[tid * 128 + m];
    sq[tid] = g_part1[tid * 128 + 64 + m];
    __syncthreads();
#pragma unroll
    for (int off = 128; off >= 1; off >>= 1) {
        if (tid < off) {
            ss[tid] += ss[tid + off];
            sq[tid] += sq[tid + off];
        }
        __syncthreads();
    }
    if (tid == 0) {
        float inv = 1.f / (float)CNT1;
        float mu = ss[0] * inv;
        float var = sq[0] * inv - mu * mu;
        float sc = gamma1[m] * rsqrtf(var + EPS);
        g_bn1[m] = sc;
        g_bn1[64 + m] = beta1[m] - mu * sc;
    }
}

// ---------------------------------------------------------------------------
// K4: tf32 GEMM2: out[p][d] = sum_m v[p][m]*W2[d][m],
//     v = leaky(bn1(select(max/min))) built once per block in smem.
// Block: 64 p x 128 d, K=64 (4 k-tiles of 16), 256 threads, 8 warps 32x32
// ---------------------------------------------------------------------------
__global__ void __launch_bounds__(256) k4_gemm2(const float* __restrict__ W2,
                                                float* __restrict__ out) {
    __shared__ float sv[64][68];    // activations [p][m]
    __shared__ float sw[128][20];   // W2 tile [d][m-chunk]
    __shared__ float sbn[128];

    int tid = threadIdx.x;
    int lane = tid & 31, w = tid >> 5;
    int grp = lane >> 2, tig = lane & 3;
    int m_base = (w >> 2) * 32;     // p offset: 0 or 32
    int n_base = (w & 3) * 32;      // d offset: 0,32,64,96
    int d0 = blockIdx.x * 128, p0 = blockIdx.y * 64;

    if (tid < 128) sbn[tid] = g_bn1[tid];
    __syncthreads();

    // build activation tile: 64 x 64 = 4096 elems, 16 per thread
#pragma unroll
    for (int i = 0; i < 16; i++) {
        int e = tid + i * 256;
        int pt = e >> 6, m = e & 63;
        float sc = sbn[m], bi = sbn[64 + m];
        float h = (sc >= 0.f) ? g_hmax[(p0 + pt) * 64 + m] : g_hmin[(p0 + pt) * 64 + m];
        float v = sc * h + bi;
        sv[pt][m] = fmaxf(v, 0.2f * v);
    }

    float acc[2][4][4];
#pragma unroll
    for (int r = 0; r < 2; r++)
#pragma unroll
        for (int j = 0; j < 4; j++)
#pragma unroll
            for (int q = 0; q < 4; q++) acc[r][j][q] = 0.f;

    for (int t = 0; t < 4; t++) {
        int k0 = t * 16;
        // load W2 tile: 128 rows x 16 cols, 2 float4 per thread
        {
            int wrow = tid >> 1;
            int seg = (tid & 1) * 8;
            *reinterpret_cast<float4*>(&sw[wrow][seg]) =
                *reinterpret_cast<const float4*>(&W2[(d0 + wrow) * 64 + k0 + seg]);
            *reinterpret_cast<float4*>(&sw[wrow][seg + 4]) =
                *reinterpret_cast<const float4*>(&W2[(d0 + wrow) * 64 + k0 + seg + 4]);
        }
        __syncthreads();

#pragma unroll
        for (int ks = 0; ks < 16; ks += 8) {
            float ah[2][4], al[2][4], bh[4][2], bl[4][2];
#pragma unroll
            for (int r = 0; r < 2; r++) {
                int mr = m_base + r * 16;
                float v0 = sv[mr + grp][k0 + ks + tig];
                float v1 = sv[mr + grp + 8][k0 + ks + tig];
                float v2 = sv[mr + grp][k0 + ks + tig + 4];
                float v3 = sv[mr + grp + 8][k0 + ks + tig + 4];
                tf32_split(v0, ah[r][0], al[r][0]);
                tf32_split(v1, ah[r][1], al[r][1]);
                tf32_split(v2, ah[r][2], al[r][2]);
                tf32_split(v3, ah[r][3], al[r][3]);
            }
#pragma unroll
            for (int j = 0; j < 4; j++) {
                int nc = n_base + j * 8 + grp;
                float v0 = sw[nc][ks + tig];
                float v1 = sw[nc][ks + tig + 4];
                tf32_split(v0, bh[j][0], bl[j][0]);
                tf32_split(v1, bh[j][1], bl[j][1]);
            }
#pragma unroll
            for (int r = 0; r < 2; r++)
#pragma unroll
                for (int j = 0; j < 4; j++) {
                    mma_tf32(acc[r][j], ah[r], bh[j]);
                    mma_tf32(acc[r][j], al[r], bh[j]);
                    mma_tf32(acc[r][j], ah[r], bl[j]);
                }
        }
        __syncthreads();
    }

#pragma unroll
    for (int r = 0; r < 2; r++) {
        int prow = p0 + m_base + r * 16 + grp;
#pragma unroll
        for (int j = 0; j < 4; j++) {
            int col = d0 + n_base + j * 8 + 2 * tig;
            *reinterpret_cast<float2*>(&out[prow * 512 + col]) =
                make_float2(acc[r][j][0], acc[r][j][1]);
            *reinterpret_cast<float2*>(&out[(prow + 8) * 512 + col]) =
                make_float2(acc[r][j][2], acc[r][j][3]);
        }
    }
}

// ---------------------------------------------------------------------------
// K4b: column partial stats over out: 64 blocks x 256 thr -> 128 partial rows
// ---------------------------------------------------------------------------
__global__ void __launch_bounds__(256) k4b_stats(const float* __restrict__ out) {
    int tid = threadIdx.x;
    int col4 = tid & 127;                 // float4 column
    int half = tid >> 7;                  // 0/1
    int r0 = blockIdx.x * 128 + half * 64;
    float s0 = 0.f, s1 = 0.f, s2 = 0.f, s3 = 0.f;
    float q0 = 0.f, q1 = 0.f, q2 = 0.f, q3 = 0.f;
#pragma unroll 4
    for (int rr = 0; rr < 64; rr++) {
        float4 v = *reinterpret_cast<const float4*>(&out[(r0 + rr) * 512 + col4 * 4]);
        s0 += v.x; q0 += v.x * v.x;
        s1 += v.y; q1 += v.y * v.y;
        s2 += v.z; q2 += v.z * v.z;
        s3 += v.w; q3 += v.w * v.w;
    }
    int prow = blockIdx.x * 2 + half;
    *reinterpret_cast<float4*>(&g_p2s[prow * 512 + col4 * 4]) = make_float4(s0, s1, s2, s3);
    *reinterpret_cast<float4*>(&g_p2q[prow * 512 + col4 * 4]) = make_float4(q0, q1, q2, q3);
}

// ---------------------------------------------------------------------------
// K5: finalize BN2 — 2 blocks x 1024 threads: 4 chunks x 256 channels
// ---------------------------------------------------------------------------
__global__ void __launch_bounds__(1024) k5_stats2(const float* __restrict__ gamma2,
                                                   const float* __restrict__ beta2) {
    __shared__ float ss[1024];
    __shared__ float sq[1024];
    int tid = threadIdx.x;
    int ch = blockIdx.x * 256 + (tid & 255);
    int chunk = tid >> 8;                     // 4 chunks of 32 rows
    float s = 0.f, q = 0.f;
#pragma unroll 4
    for (int r = 0; r < 32; r++) {
        int row = chunk * 32 + r;
        s += g_p2s[row * 512 + ch];
        q += g_p2q[row * 512 + ch];
    }
    ss[tid] = s;
    sq[tid] = q;
    __syncthreads();
    if (tid < 256) {
        float ts = 0.f, tq = 0.f;
#pragma unroll
        for (int c = 0; c < 4; c++) {
            ts += ss[tid + 256 * c];
            tq += sq[tid + 256 * c];
        }
        float inv = 1.f / (float)CNT2;
        float mu = ts * inv;
        float var = tq * inv - mu * mu;
        float sc = gamma2[ch] * rsqrtf(var + EPS);
        g_bn2[ch] = sc;
        g_bn2[512 + ch] = beta2[ch] - mu * sc;
    }
}

// ---------------------------------------------------------------------------
// K6: in-place affine + leaky on out (float4 vectorized)
// ---------------------------------------------------------------------------
__global__ void __launch_bounds__(256) k6_final(float* __restrict__ out) {
    int i = blockIdx.x * 256 + threadIdx.x;   // float4 index, 1048576 total
    float4 v = reinterpret_cast<float4*>(out)[i];
    int d = (i * 4) & 511;
    float s0 = g_bn2[d],       s1 = g_bn2[d + 1],   s2 = g_bn2[d + 2],   s3 = g_bn2[d + 3];
    float b0 = g_bn2[512 + d], b1 = g_bn2[513 + d], b2 = g_bn2[514 + d], b3 = g_bn2[515 + d];
    float t0 = s0 * v.x + b0;
    float t1 = s1 * v.y + b1;
    float t2 = s2 * v.z + b2;
    float t3 = s3 * v.w + b3;
    v.x = fmaxf(t0, 0.2f * t0);
    v.y = fmaxf(t1, 0.2f * t1);
    v.z = fmaxf(t2, 0.2f * t2);
    v.w = fmaxf(t3, 0.2f * t3);
    reinterpret_cast<float4*>(out)[i] = v;
}

// ---------------------------------------------------------------------------
extern "C" void kernel_launch(void* const* d_in, const int* in_sizes, int n_in,
                              void* d_out, int out_size) {
    const float* x      = (const float*)d_in[0];
    const int*   idx    = (const int*)  d_in[1];
    const float* W1     = (const float*)d_in[2];
    const float* gamma1 = (const float*)d_in[3];
    const float* beta1  = (const float*)d_in[4];
    const float* W2     = (const float*)d_in[5];
    const float* gamma2 = (const float*)d_in[6];
    const float* beta2  = (const float*)d_in[7];
    float* out = (float*)d_out;

    k0_prepw<<<256, 256>>>(W1);
    k1_gemm1<<<128, 256>>>(x);
    k2_gather<<<256, 256>>>(idx);
    k3_stats1<<<64, 256>>>(gamma1, beta1);
    k4_gemm2<<<dim3(4, 128), 256>>>(W2, out);
    k4b_stats<<<64, 256>>>(out);
    k5_stats2<<<2, 1024>>>(gamma2, beta2);
    k6_final<<<4096, 256>>>(out);
}